// round 4
// baseline (speedup 1.0000x reference)
#include <cuda_runtime.h>
#include <cuda_fp16.h>
#include <math.h>

#define TT 150
#define BB 64
#define DD 2000
#define SS 3000
#define EE 100000
#define STPB 32
#define NBLK ((SS + STPB - 1) / STPB)   // 94 blocks, 512 threads each

// ---------------- scratch (__device__ globals; re-initialized every call) ----
__device__ __half g_Pt[(size_t)TT * DD * BB];  // exp(input) fp16, [T][D][B]
__device__ __half g_A[2][SS * BB];             // ping-pong normalized forward scores (fp16)
__device__ float  g_csum[(TT + 1) * BB];       // s_t[b] = sum_s A_t[s,b] (fp32)
__device__ int    g_cnt[SS];
__device__ int    g_rowptr[SS + 1];
__device__ int    g_cursor[SS];
__device__ int2   g_meta[EE];                  // {from<<11|pdf, exp(w) fp32 bits} CSR by to
__device__ unsigned g_count;
__device__ unsigned g_phase;

// ---------------- precompute: exp + transpose input [T][B][D] -> [T][D][B] ---
__global__ void k_exp_T(const float* __restrict__ in) {
    __shared__ float tile[32][33];
    int t  = blockIdx.z;
    int d0 = blockIdx.x * 32;
    int b0 = blockIdx.y * 32;
    int tx = threadIdx.x, ty = threadIdx.y;
    int d = d0 + tx, b = b0 + ty;
    float v = 0.0f;
    if (d < DD) v = in[((size_t)t * BB + b) * DD + d];
    tile[ty][tx] = __expf(v);
    __syncthreads();
    int dd = d0 + ty, bb = b0 + tx;
    if (dd < DD) g_Pt[((size_t)t * DD + dd) * BB + bb] = __float2half_rn(tile[tx][ty]);
}

// ---------------- init ------------------------------------------------------
__global__ void k_init(const float* __restrict__ init_logp) {
    int i = blockIdx.x * blockDim.x + threadIdx.x;
    if (i == 0) { g_count = 0; g_phase = 0; }
    if (i < SS) { g_cnt[i] = 0; g_cursor[i] = 0; }
    if (i < (TT + 1) * BB) g_csum[i] = 0.0f;
    if (i < SS * BB) {
        int s = i >> 6;
        g_A[0][i] = __float2half_rn(__expf(init_logp[s]));
    }
}

__global__ void k_hist(const int* __restrict__ to_state) {
    int i = blockIdx.x * blockDim.x + threadIdx.x;
    if (i < EE) atomicAdd(&g_cnt[to_state[i]], 1);
}

// single-block exclusive scan of g_cnt -> g_rowptr; also csum[0][b]
__global__ void k_scan(const float* __restrict__ init_logp) {
    __shared__ int sh[1024];
    __shared__ float shf[1024];
    int tid = threadIdx.x;
    const int CH = 3;
    int base_i = tid * CH;
    int local[CH];
    int sum = 0;
    #pragma unroll
    for (int j = 0; j < CH; j++) {
        int idx = base_i + j;
        int v = (idx < SS) ? g_cnt[idx] : 0;
        local[j] = sum;
        sum += v;
    }
    sh[tid] = sum;
    __syncthreads();
    for (int off = 1; off < 1024; off <<= 1) {
        int v = (tid >= off) ? sh[tid - off] : 0;
        __syncthreads();
        sh[tid] += v;
        __syncthreads();
    }
    int excl = sh[tid] - sum;
    #pragma unroll
    for (int j = 0; j < CH; j++) {
        int idx = base_i + j;
        if (idx < SS) g_rowptr[idx] = excl + local[j];
    }
    if (tid == 0) g_rowptr[SS] = EE;

    // csum[0][b]: sum of the fp16-rounded A0 values (consistent with stored A0)
    float fs = 0.0f;
    for (int idx = tid; idx < SS; idx += 1024)
        fs += __half2float(__float2half_rn(__expf(init_logp[idx])));
    shf[tid] = fs;
    __syncthreads();
    for (int off = 512; off > 0; off >>= 1) {
        if (tid < off) shf[tid] += shf[tid + off];
        __syncthreads();
    }
    if (tid < BB) g_csum[tid] = shf[0];
}

__global__ void k_scatter(const int* __restrict__ to_state,
                          const int* __restrict__ from_state,
                          const int* __restrict__ pdf_id,
                          const float* __restrict__ trans_logw) {
    int i = blockIdx.x * blockDim.x + threadIdx.x;
    if (i >= EE) return;
    int to = to_state[i];
    int p = g_rowptr[to] + atomicAdd(&g_cursor[to], 1);
    int packed = (from_state[i] << 11) | pdf_id[i];
    g_meta[p] = make_int2(packed, __float_as_int(__expf(trans_logw[i])));
}

// ---------------- persistent forward recursion -------------------------------
__device__ __forceinline__ float4 h4_to_f4_cg(const __half* p) {
    int2 v = __ldcg((const int2*)p);                 // 8B = 4 halves, L2-coherent
    __half2 h0 = *(__half2*)&v.x;
    __half2 h1 = *(__half2*)&v.y;
    float2 f0 = __half22float2(h0);
    float2 f1 = __half22float2(h1);
    return make_float4(f0.x, f0.y, f1.x, f1.y);
}
__device__ __forceinline__ float4 h4_to_f4(const __half* p) {
    int2 v = *(const int2*)p;                        // P: written pre-launch, L1 ok
    __half2 h0 = *(__half2*)&v.x;
    __half2 h1 = *(__half2*)&v.y;
    float2 f0 = __half22float2(h0);
    float2 f1 = __half22float2(h1);
    return make_float4(f0.x, f0.y, f1.x, f1.y);
}

__global__ void __launch_bounds__(512) k_forward() {
    int tid = threadIdx.x;
    int bq = (tid & 15) << 2;                  // batch base (in elements)
    int sl = tid >> 4;                         // state slot 0..31
    int s  = blockIdx.x * STPB + sl;

    int r0 = 0, r1 = 0;
    if (s < SS) { r0 = __ldg(&g_rowptr[s]); r1 = __ldg(&g_rowptr[s + 1]); }

    __shared__ float4 red[512];

    for (int t = 0; t < TT; t++) {
        const __half* __restrict__ Ap = g_A[t & 1];
        __half*       __restrict__ An = g_A[(t + 1) & 1];
        const __half* __restrict__ P  = g_Pt + (size_t)t * (DD * BB);

        float4 c = __ldcg((const float4*)&g_csum[t * BB + bq]);
        float4 invc = make_float4(__frcp_rn(c.x), __frcp_rn(c.y),
                                  __frcp_rn(c.z), __frcp_rn(c.w));

        float4 acc = make_float4(0.f, 0.f, 0.f, 0.f);
        int e = r0;
        for (; e + 4 <= r1; e += 4) {
            int2 m0 = __ldg(&g_meta[e]);
            int2 m1 = __ldg(&g_meta[e + 1]);
            int2 m2 = __ldg(&g_meta[e + 2]);
            int2 m3 = __ldg(&g_meta[e + 3]);
            float4 a0 = h4_to_f4_cg(&Ap[((m0.x >> 11) << 6) + bq]);
            float4 a1 = h4_to_f4_cg(&Ap[((m1.x >> 11) << 6) + bq]);
            float4 a2 = h4_to_f4_cg(&Ap[((m2.x >> 11) << 6) + bq]);
            float4 a3 = h4_to_f4_cg(&Ap[((m3.x >> 11) << 6) + bq]);
            float4 p0 = h4_to_f4(&P[((m0.x & 2047) << 6) + bq]);
            float4 p1 = h4_to_f4(&P[((m1.x & 2047) << 6) + bq]);
            float4 p2 = h4_to_f4(&P[((m2.x & 2047) << 6) + bq]);
            float4 p3 = h4_to_f4(&P[((m3.x & 2047) << 6) + bq]);
            float w0 = __int_as_float(m0.y), w1 = __int_as_float(m1.y);
            float w2 = __int_as_float(m2.y), w3 = __int_as_float(m3.y);
            acc.x = fmaf(w0 * a0.x, p0.x, acc.x);
            acc.y = fmaf(w0 * a0.y, p0.y, acc.y);
            acc.z = fmaf(w0 * a0.z, p0.z, acc.z);
            acc.w = fmaf(w0 * a0.w, p0.w, acc.w);
            acc.x = fmaf(w1 * a1.x, p1.x, acc.x);
            acc.y = fmaf(w1 * a1.y, p1.y, acc.y);
            acc.z = fmaf(w1 * a1.z, p1.z, acc.z);
            acc.w = fmaf(w1 * a1.w, p1.w, acc.w);
            acc.x = fmaf(w2 * a2.x, p2.x, acc.x);
            acc.y = fmaf(w2 * a2.y, p2.y, acc.y);
            acc.z = fmaf(w2 * a2.z, p2.z, acc.z);
            acc.w = fmaf(w2 * a2.w, p2.w, acc.w);
            acc.x = fmaf(w3 * a3.x, p3.x, acc.x);
            acc.y = fmaf(w3 * a3.y, p3.y, acc.y);
            acc.z = fmaf(w3 * a3.z, p3.z, acc.z);
            acc.w = fmaf(w3 * a3.w, p3.w, acc.w);
        }
        for (; e < r1; e++) {
            int2 m = __ldg(&g_meta[e]);
            float4 a = h4_to_f4_cg(&Ap[((m.x >> 11) << 6) + bq]);
            float4 p = h4_to_f4(&P[((m.x & 2047) << 6) + bq]);
            float w = __int_as_float(m.y);
            acc.x = fmaf(w * a.x, p.x, acc.x);
            acc.y = fmaf(w * a.y, p.y, acc.y);
            acc.z = fmaf(w * a.z, p.z, acc.z);
            acc.w = fmaf(w * a.w, p.w, acc.w);
        }

        float4 val = make_float4(acc.x * invc.x, acc.y * invc.y,
                                 acc.z * invc.z, acc.w * invc.w);
        if (s < SS) {
            __half2 h0 = __floats2half2_rn(val.x, val.y);
            __half2 h1 = __floats2half2_rn(val.z, val.w);
            int2 packed = make_int2(*(int*)&h0, *(int*)&h1);
            __stcg((int2*)&An[s * BB + bq], packed);
        }

        // block reduction over the 32 states -> csum[t+1][b]
        red[tid] = val;
        __syncthreads();
        #pragma unroll
        for (int off = 256; off >= 16; off >>= 1) {
            if (tid < off) {
                float4 o = red[tid + off];
                red[tid].x += o.x; red[tid].y += o.y;
                red[tid].z += o.z; red[tid].w += o.w;
            }
            __syncthreads();
        }
        if (tid < 16) {
            float4 v = red[tid];
            float* dst = &g_csum[(t + 1) * BB + (tid << 2)];
            atomicAdd(dst + 0, v.x);
            atomicAdd(dst + 1, v.y);
            atomicAdd(dst + 2, v.z);
            atomicAdd(dst + 3, v.w);
        }
        __syncthreads();   // all stores/atomics of this block issued before arrive

        // ---- grid barrier (release/acquire) ----
        if (tid == 0) {
            unsigned target = (unsigned)(t + 1);
            unsigned old;
            asm volatile("atom.add.release.gpu.global.u32 %0, [%1], 1;"
                         : "=r"(old) : "l"(&g_count) : "memory");
            if (old == NBLK - 1) {
                g_count = 0;
                asm volatile("st.release.gpu.global.u32 [%0], %1;"
                             :: "l"(&g_phase), "r"(target) : "memory");
            } else {
                unsigned ph;
                do {
                    asm volatile("ld.acquire.gpu.global.u32 %0, [%1];"
                                 : "=r"(ph) : "l"(&g_phase) : "memory");
                    if (ph < target) __nanosleep(32);
                } while (ph < target);
            }
        }
        __syncthreads();
    }
}

// ---------------- final: objf = sum_b [ log(A_T . F) + sum_t log s_t ] ------
__global__ void k_final(const float* __restrict__ final_logp, float* __restrict__ out) {
    __shared__ float red[256];
    const __half* At = g_A[TT & 1];
    int b = threadIdx.x & 63;
    int c = threadIdx.x >> 6;
    float acc = 0.0f;
    for (int s = c; s < SS; s += 4)
        acc += __half2float(At[s * BB + b]) * expf(final_logp[s]);
    red[threadIdx.x] = acc;
    __syncthreads();
    if (c == 0) {
        float dot = red[b] + red[64 + b] + red[128 + b] + red[192 + b];
        float lg = logf(dot);
        for (int t = 0; t < TT; t++) lg += logf(g_csum[t * BB + b]);
        red[b] = lg;
    }
    __syncthreads();
    if (threadIdx.x == 0) {
        float s = 0.0f;
        for (int bb = 0; bb < BB; bb++) s += red[bb];
        out[0] = s;
    }
}

// ---------------- launch -----------------------------------------------------
extern "C" void kernel_launch(void* const* d_in, const int* in_sizes, int n_in,
                              void* d_out, int out_size) {
    const float* input      = (const float*)d_in[0];
    const float* trans_logw = (const float*)d_in[1];
    const float* init_logp  = (const float*)d_in[2];
    const float* final_logp = (const float*)d_in[3];
    const int*   from_state = (const int*)d_in[4];
    const int*   to_state   = (const int*)d_in[5];
    const int*   pdf_id     = (const int*)d_in[6];
    float* out = (float*)d_out;

    dim3 gT((DD + 31) / 32, BB / 32, TT);
    k_exp_T<<<gT, dim3(32, 32)>>>(input);
    k_init<<<(SS * BB + 255) / 256, 256>>>(init_logp);
    k_hist<<<(EE + 255) / 256, 256>>>(to_state);
    k_scan<<<1, 1024>>>(init_logp);
    k_scatter<<<(EE + 255) / 256, 256>>>(to_state, from_state, pdf_id, trans_logw);
    k_forward<<<NBLK, 512>>>();
    k_final<<<1, 256>>>(final_logp, out);
}

// round 6
// speedup vs baseline: 1.2318x; 1.2318x over previous
#include <cuda_runtime.h>
#include <cuda_fp16.h>
#include <math.h>

#define TT 150
#define BB 64
#define DD 2000
#define SS 3000
#define EE 100000
#define WPB 8                            // warps (=states) per block
#define NBLK (SS / WPB)                  // 375 blocks x 256 threads

// ---------------- scratch (__device__ globals; re-initialized every call) ----
__device__ __half g_Pt[(size_t)TT * DD * BB];  // exp(input) fp16, [T][D][B]
__device__ __half g_A[2][SS * BB];             // ping-pong normalized forward scores (fp16)
__device__ float  g_csum[(TT + 1) * BB];       // s_t[b] (fp32)
__device__ int    g_cnt[SS];
__device__ int    g_rowptr[SS + 1];
__device__ int    g_cursor[SS];
__device__ int2   g_meta[EE];                  // {from<<11|pdf, exp(w) fp32 bits} CSR by to
__device__ unsigned g_count;
__device__ unsigned g_phase;

// ---------------- precompute: exp + transpose input [T][B][D] -> [T][D][B] ---
__global__ void k_exp_T(const float* __restrict__ in) {
    __shared__ float tile[32][33];
    int t  = blockIdx.z;
    int d0 = blockIdx.x * 32;
    int b0 = blockIdx.y * 32;
    int tx = threadIdx.x, ty = threadIdx.y;
    int d = d0 + tx, b = b0 + ty;
    float v = 0.0f;
    if (d < DD) v = in[((size_t)t * BB + b) * DD + d];
    tile[ty][tx] = __expf(v);
    __syncthreads();
    int dd = d0 + ty, bb = b0 + tx;
    if (dd < DD) g_Pt[((size_t)t * DD + dd) * BB + bb] = __float2half_rn(tile[tx][ty]);
}

// ---------------- init ------------------------------------------------------
__global__ void k_init(const float* __restrict__ init_logp) {
    int i = blockIdx.x * blockDim.x + threadIdx.x;
    if (i == 0) { g_count = 0; g_phase = 0; }
    if (i < SS) { g_cnt[i] = 0; g_cursor[i] = 0; }
    if (i < (TT + 1) * BB) g_csum[i] = 0.0f;
    if (i < SS * BB) {
        int s = i >> 6;
        g_A[0][i] = __float2half_rn(__expf(init_logp[s]));
    }
}

__global__ void k_hist(const int* __restrict__ to_state) {
    int i = blockIdx.x * blockDim.x + threadIdx.x;
    if (i < EE) atomicAdd(&g_cnt[to_state[i]], 1);
}

// single-block exclusive scan of g_cnt -> g_rowptr; also csum[0][b]
__global__ void k_scan(const float* __restrict__ init_logp) {
    __shared__ int sh[1024];
    __shared__ float shf[1024];
    int tid = threadIdx.x;
    const int CH = 3;
    int base_i = tid * CH;
    int local[CH];
    int sum = 0;
    #pragma unroll
    for (int j = 0; j < CH; j++) {
        int idx = base_i + j;
        int v = (idx < SS) ? g_cnt[idx] : 0;
        local[j] = sum;
        sum += v;
    }
    sh[tid] = sum;
    __syncthreads();
    for (int off = 1; off < 1024; off <<= 1) {
        int v = (tid >= off) ? sh[tid - off] : 0;
        __syncthreads();
        sh[tid] += v;
        __syncthreads();
    }
    int excl = sh[tid] - sum;
    #pragma unroll
    for (int j = 0; j < CH; j++) {
        int idx = base_i + j;
        if (idx < SS) g_rowptr[idx] = excl + local[j];
    }
    if (tid == 0) g_rowptr[SS] = EE;

    // csum[0][b]: sum of the fp16-rounded A0 values
    float fs = 0.0f;
    for (int idx = tid; idx < SS; idx += 1024)
        fs += __half2float(__float2half_rn(__expf(init_logp[idx])));
    shf[tid] = fs;
    __syncthreads();
    for (int off = 512; off > 0; off >>= 1) {
        if (tid < off) shf[tid] += shf[tid + off];
        __syncthreads();
    }
    if (tid < BB) g_csum[tid] = shf[0];
}

__global__ void k_scatter(const int* __restrict__ to_state,
                          const int* __restrict__ from_state,
                          const int* __restrict__ pdf_id,
                          const float* __restrict__ trans_logw) {
    int i = blockIdx.x * blockDim.x + threadIdx.x;
    if (i >= EE) return;
    int to = to_state[i];
    int p = g_rowptr[to] + atomicAdd(&g_cursor[to], 1);
    int packed = (from_state[i] << 11) | pdf_id[i];
    g_meta[p] = make_int2(packed, __float_as_int(__expf(trans_logw[i])));
}

// ---------------- persistent forward recursion -------------------------------
// One warp per state. Lane covers 2 batch elems (half2). No intra-warp divergence.
__device__ __forceinline__ float2 h2f2_cg(const __half* p) {
    int v;
    asm volatile("ld.global.cg.b32 %0, [%1];" : "=r"(v) : "l"(p));
    return __half22float2(*(__half2*)&v);
}
__device__ __forceinline__ float2 h2f2(const __half* p) {
    int v = *(const int*)p;
    return __half22float2(*(__half2*)&v);
}

__global__ void __launch_bounds__(256) k_forward() {
    int tid  = threadIdx.x;
    int warp = tid >> 5;
    int lane = tid & 31;
    int boff = lane << 1;                       // batch offset (2 per lane)
    int s = blockIdx.x * WPB + warp;            // exact: 375*8 = 3000

    int r0 = __ldg(&g_rowptr[s]);
    int r1 = __ldg(&g_rowptr[s + 1]);

    __shared__ float sh[WPB][BB];

    for (int t = 0; t < TT; t++) {
        const __half* __restrict__ Ap = g_A[t & 1];
        __half*       __restrict__ An = g_A[(t + 1) & 1];
        const __half* __restrict__ P  = g_Pt + (size_t)t * (DD * BB);

        float2 c;
        asm volatile("ld.global.cg.v2.f32 {%0,%1}, [%2];"
                     : "=f"(c.x), "=f"(c.y) : "l"(&g_csum[t * BB + boff]));
        float2 invc = make_float2(__frcp_rn(c.x), __frcp_rn(c.y));

        float2 acc = make_float2(0.f, 0.f);
        int e = r0;
        for (; e + 4 <= r1; e += 4) {
            int2 m0 = __ldg(&g_meta[e]);
            int2 m1 = __ldg(&g_meta[e + 1]);
            int2 m2 = __ldg(&g_meta[e + 2]);
            int2 m3 = __ldg(&g_meta[e + 3]);
            float2 a0 = h2f2_cg(&Ap[((m0.x >> 11) << 6) + boff]);
            float2 a1 = h2f2_cg(&Ap[((m1.x >> 11) << 6) + boff]);
            float2 a2 = h2f2_cg(&Ap[((m2.x >> 11) << 6) + boff]);
            float2 a3 = h2f2_cg(&Ap[((m3.x >> 11) << 6) + boff]);
            float2 p0 = h2f2(&P[((m0.x & 2047) << 6) + boff]);
            float2 p1 = h2f2(&P[((m1.x & 2047) << 6) + boff]);
            float2 p2 = h2f2(&P[((m2.x & 2047) << 6) + boff]);
            float2 p3 = h2f2(&P[((m3.x & 2047) << 6) + boff]);
            float w0 = __int_as_float(m0.y), w1 = __int_as_float(m1.y);
            float w2 = __int_as_float(m2.y), w3 = __int_as_float(m3.y);
            acc.x = fmaf(w0 * a0.x, p0.x, acc.x);
            acc.y = fmaf(w0 * a0.y, p0.y, acc.y);
            acc.x = fmaf(w1 * a1.x, p1.x, acc.x);
            acc.y = fmaf(w1 * a1.y, p1.y, acc.y);
            acc.x = fmaf(w2 * a2.x, p2.x, acc.x);
            acc.y = fmaf(w2 * a2.y, p2.y, acc.y);
            acc.x = fmaf(w3 * a3.x, p3.x, acc.x);
            acc.y = fmaf(w3 * a3.y, p3.y, acc.y);
        }
        for (; e < r1; e++) {
            int2 m = __ldg(&g_meta[e]);
            float2 a = h2f2_cg(&Ap[((m.x >> 11) << 6) + boff]);
            float2 p = h2f2(&P[((m.x & 2047) << 6) + boff]);
            float w = __int_as_float(m.y);
            acc.x = fmaf(w * a.x, p.x, acc.x);
            acc.y = fmaf(w * a.y, p.y, acc.y);
        }

        float2 val = make_float2(acc.x * invc.x, acc.y * invc.y);
        {
            __half2 h = __floats2half2_rn(val.x, val.y);
            int bits = *(int*)&h;
            asm volatile("st.global.cg.b32 [%0], %1;"
                         :: "l"(&An[s * BB + boff]), "r"(bits));
        }

        sh[warp][boff] = val.x;
        sh[warp][boff + 1] = val.y;
        __syncthreads();
        if (tid < BB) {
            float v = sh[0][tid];
            #pragma unroll
            for (int w = 1; w < WPB; w++) v += sh[w][tid];
            atomicAdd(&g_csum[(t + 1) * BB + tid], v);
        }
        __syncthreads();

        // ---- grid barrier (release/acquire) ----
        if (tid == 0) {
            unsigned target = (unsigned)(t + 1);
            unsigned old;
            asm volatile("atom.add.release.gpu.global.u32 %0, [%1], 1;"
                         : "=r"(old) : "l"(&g_count) : "memory");
            if (old == NBLK - 1) {
                g_count = 0;
                asm volatile("st.release.gpu.global.u32 [%0], %1;"
                             :: "l"(&g_phase), "r"(target) : "memory");
            } else {
                unsigned ph;
                do {
                    asm volatile("ld.acquire.gpu.global.u32 %0, [%1];"
                                 : "=r"(ph) : "l"(&g_phase) : "memory");
                    if (ph < target) __nanosleep(32);
                } while (ph < target);
            }
        }
        __syncthreads();
    }
}

// ---------------- final: objf = sum_b [ log(A_T . F) + sum_t log s_t ] ------
__global__ void k_final(const float* __restrict__ final_logp, float* __restrict__ out) {
    __shared__ float red[256];
    const __half* At = g_A[TT & 1];
    int b = threadIdx.x & 63;
    int c = threadIdx.x >> 6;
    float acc = 0.0f;
    for (int s = c; s < SS; s += 4)
        acc += __half2float(At[s * BB + b]) * expf(final_logp[s]);
    red[threadIdx.x] = acc;
    __syncthreads();
    if (c == 0) {
        float dot = red[b] + red[64 + b] + red[128 + b] + red[192 + b];
        float lg = logf(dot);
        for (int t = 0; t < TT; t++) lg += logf(g_csum[t * BB + b]);
        red[b] = lg;
    }
    __syncthreads();
    if (threadIdx.x == 0) {
        float s = 0.0f;
        for (int bb = 0; bb < BB; bb++) s += red[bb];
        out[0] = s;
    }
}

// ---------------- launch -----------------------------------------------------
extern "C" void kernel_launch(void* const* d_in, const int* in_sizes, int n_in,
                              void* d_out, int out_size) {
    const float* input      = (const float*)d_in[0];
    const float* trans_logw = (const float*)d_in[1];
    const float* init_logp  = (const float*)d_in[2];
    const float* final_logp = (const float*)d_in[3];
    const int*   from_state = (const int*)d_in[4];
    const int*   to_state   = (const int*)d_in[5];
    const int*   pdf_id     = (const int*)d_in[6];
    float* out = (float*)d_out;

    dim3 gT((DD + 31) / 32, BB / 32, TT);
    k_exp_T<<<gT, dim3(32, 32)>>>(input);
    k_init<<<(SS * BB + 255) / 256, 256>>>(init_logp);
    k_hist<<<(EE + 255) / 256, 256>>>(to_state);
    k_scan<<<1, 1024>>>(init_logp);
    k_scatter<<<(EE + 255) / 256, 256>>>(to_state, from_state, pdf_id, trans_logw);
    k_forward<<<NBLK, 256>>>();
    k_final<<<1, 256>>>(final_logp, out);
}

// round 7
// speedup vs baseline: 1.2829x; 1.0415x over previous
#include <cuda_runtime.h>
#include <cuda_fp16.h>
#include <math.h>

#define TT 150
#define BB 64
#define DD 2000
#define SS 3000
#define EE 100000
#define NBLK 148                         // one CTA per SM
#define NTHR 1024                        // 32 warps; warp-per-state, <=21 states/block

// ---------------- scratch (__device__ globals; re-initialized every call) ----
__device__ __half g_Pt[(size_t)TT * DD * BB];  // exp(input) fp16, [T][D][B]
__device__ __half g_A[2][SS * BB];             // ping-pong normalized forward scores (fp16)
__device__ float  g_csum[(TT + 1) * BB];       // s_t[b] (fp32)
__device__ int    g_cnt[SS];
__device__ int    g_rowptr[SS + 1];
__device__ int    g_cursor[SS];
__device__ int2   g_meta[EE];                  // {from<<11|pdf, exp(w) fp32 bits} CSR by to

// barrier words on separate 256B-aligned lines (different L2 lines AND LTS slices)
struct __align__(256) BarLine { unsigned v; unsigned pad[63]; };
__device__ BarLine g_count;
__device__ BarLine g_phase;

// ---------------- #1: exp + transpose input [T][B][D] -> [T][D][B] ----------
// block (0,0,0) additionally zeroes counters/csum/barrier state.
__global__ void k_exp_T(const float* __restrict__ in) {
    __shared__ float tile[32][33];
    int t  = blockIdx.z;
    int d0 = blockIdx.x * 32;
    int b0 = blockIdx.y * 32;
    int tx = threadIdx.x, ty = threadIdx.y;
    int d = d0 + tx, b = b0 + ty;
    float v = 0.0f;
    if (d < DD) v = in[((size_t)t * BB + b) * DD + d];
    tile[ty][tx] = __expf(v);
    __syncthreads();
    int dd = d0 + ty, bb = b0 + tx;
    if (dd < DD) g_Pt[((size_t)t * DD + dd) * BB + bb] = __float2half_rn(tile[tx][ty]);

    if (blockIdx.x == 0 && blockIdx.y == 0 && blockIdx.z == 0) {
        int tid = ty * 32 + tx;                  // 0..1023
        if (tid == 0) { g_count.v = 0; g_phase.v = 0; }
        for (int i = tid; i < SS; i += 1024) { g_cnt[i] = 0; g_cursor[i] = 0; }
        for (int i = tid; i < (TT + 1) * BB; i += 1024) g_csum[i] = 0.0f;
    }
}

// ---------------- #2: A0 init + arc histogram -------------------------------
__global__ void k_init_hist(const float* __restrict__ init_logp,
                            const int* __restrict__ to_state) {
    int i = blockIdx.x * blockDim.x + threadIdx.x;
    if (i < SS * BB) {
        int s = i >> 6;
        g_A[0][i] = __float2half_rn(__expf(init_logp[s]));
    }
    if (i < EE) atomicAdd(&g_cnt[to_state[i]], 1);
}

// ---------------- #3: scan + csum0 + scatter (single block, 1024 thr) -------
__global__ void k_scan_scatter(const float* __restrict__ init_logp,
                               const int* __restrict__ to_state,
                               const int* __restrict__ from_state,
                               const int* __restrict__ pdf_id,
                               const float* __restrict__ trans_logw) {
    __shared__ int sh[1024];
    __shared__ float shf[1024];
    int tid = threadIdx.x;
    const int CH = 3;
    int base_i = tid * CH;
    int local[CH];
    int sum = 0;
    #pragma unroll
    for (int j = 0; j < CH; j++) {
        int idx = base_i + j;
        int v = (idx < SS) ? g_cnt[idx] : 0;
        local[j] = sum;
        sum += v;
    }
    sh[tid] = sum;
    __syncthreads();
    for (int off = 1; off < 1024; off <<= 1) {
        int v = (tid >= off) ? sh[tid - off] : 0;
        __syncthreads();
        sh[tid] += v;
        __syncthreads();
    }
    int excl = sh[tid] - sum;
    #pragma unroll
    for (int j = 0; j < CH; j++) {
        int idx = base_i + j;
        if (idx < SS) g_rowptr[idx] = excl + local[j];
    }
    if (tid == 0) g_rowptr[SS] = EE;

    // csum[0][b]: sum of fp16-rounded A0 values
    float fs = 0.0f;
    for (int idx = tid; idx < SS; idx += 1024)
        fs += __half2float(__float2half_rn(__expf(init_logp[idx])));
    shf[tid] = fs;
    __syncthreads();
    for (int off = 512; off > 0; off >>= 1) {
        if (tid < off) shf[tid] += shf[tid + off];
        __syncthreads();
    }
    if (tid < BB) g_csum[tid] = shf[0];
    __syncthreads();

    // scatter arcs into CSR order
    for (int i = tid; i < EE; i += 1024) {
        int to = to_state[i];
        int p = g_rowptr[to] + atomicAdd(&g_cursor[to], 1);
        int packed = (from_state[i] << 11) | pdf_id[i];
        g_meta[p] = make_int2(packed, __float_as_int(__expf(trans_logw[i])));
    }
}

// ---------------- #4: persistent forward recursion ---------------------------
__device__ __forceinline__ float2 h2f2_cg(const __half* p) {
    int v;
    asm volatile("ld.global.cg.b32 %0, [%1];" : "=r"(v) : "l"(p));
    return __half22float2(*(__half2*)&v);
}
__device__ __forceinline__ float2 h2f2(const __half* p) {
    int v = *(const int*)p;
    return __half22float2(*(__half2*)&v);
}

__global__ void __launch_bounds__(NTHR, 1) k_forward() {
    int tid  = threadIdx.x;
    int warp = tid >> 5;
    int lane = tid & 31;
    int boff = lane << 1;

    int s_begin = (blockIdx.x * SS) / NBLK;
    int s_end   = ((blockIdx.x + 1) * SS) / NBLK;
    int nw = s_end - s_begin;                   // 20 or 21
    int s = s_begin + warp;
    bool active = warp < nw;

    int r0 = 0, r1 = 0;
    if (active) { r0 = __ldg(&g_rowptr[s]); r1 = __ldg(&g_rowptr[s + 1]); }

    __shared__ float sh[32][BB];

    for (int t = 0; t < TT; t++) {
        const __half* __restrict__ Ap = g_A[t & 1];
        __half*       __restrict__ An = g_A[(t + 1) & 1];
        const __half* __restrict__ P  = g_Pt + (size_t)t * (DD * BB);

        float2 c;
        asm volatile("ld.global.cg.v2.f32 {%0,%1}, [%2];"
                     : "=f"(c.x), "=f"(c.y) : "l"(&g_csum[t * BB + boff]));
        float2 invc = make_float2(__frcp_rn(c.x), __frcp_rn(c.y));

        float2 acc = make_float2(0.f, 0.f);
        int e = r0;
        for (; e + 4 <= r1; e += 4) {
            int2 m0 = __ldg(&g_meta[e]);
            int2 m1 = __ldg(&g_meta[e + 1]);
            int2 m2 = __ldg(&g_meta[e + 2]);
            int2 m3 = __ldg(&g_meta[e + 3]);
            float2 a0 = h2f2_cg(&Ap[((m0.x >> 11) << 6) + boff]);
            float2 a1 = h2f2_cg(&Ap[((m1.x >> 11) << 6) + boff]);
            float2 a2 = h2f2_cg(&Ap[((m2.x >> 11) << 6) + boff]);
            float2 a3 = h2f2_cg(&Ap[((m3.x >> 11) << 6) + boff]);
            float2 p0 = h2f2(&P[((m0.x & 2047) << 6) + boff]);
            float2 p1 = h2f2(&P[((m1.x & 2047) << 6) + boff]);
            float2 p2 = h2f2(&P[((m2.x & 2047) << 6) + boff]);
            float2 p3 = h2f2(&P[((m3.x & 2047) << 6) + boff]);
            float w0 = __int_as_float(m0.y), w1 = __int_as_float(m1.y);
            float w2 = __int_as_float(m2.y), w3 = __int_as_float(m3.y);
            acc.x = fmaf(w0 * a0.x, p0.x, acc.x);
            acc.y = fmaf(w0 * a0.y, p0.y, acc.y);
            acc.x = fmaf(w1 * a1.x, p1.x, acc.x);
            acc.y = fmaf(w1 * a1.y, p1.y, acc.y);
            acc.x = fmaf(w2 * a2.x, p2.x, acc.x);
            acc.y = fmaf(w2 * a2.y, p2.y, acc.y);
            acc.x = fmaf(w3 * a3.x, p3.x, acc.x);
            acc.y = fmaf(w3 * a3.y, p3.y, acc.y);
        }
        for (; e < r1; e++) {
            int2 m = __ldg(&g_meta[e]);
            float2 a = h2f2_cg(&Ap[((m.x >> 11) << 6) + boff]);
            float2 p = h2f2(&P[((m.x & 2047) << 6) + boff]);
            float w = __int_as_float(m.y);
            acc.x = fmaf(w * a.x, p.x, acc.x);
            acc.y = fmaf(w * a.y, p.y, acc.y);
        }

        float2 val = make_float2(acc.x * invc.x, acc.y * invc.y);
        if (active) {
            __half2 h = __floats2half2_rn(val.x, val.y);
            int bits = *(int*)&h;
            asm volatile("st.global.cg.b32 [%0], %1;"
                         :: "l"(&An[s * BB + boff]), "r"(bits));
            sh[warp][boff]     = val.x;
            sh[warp][boff + 1] = val.y;
        }
        __syncthreads();
        if (tid < BB) {
            float v = 0.0f;
            for (int w = 0; w < nw; w++) v += sh[w][tid];
            atomicAdd(&g_csum[(t + 1) * BB + tid], v);
        }
        __syncthreads();

        // ---- grid barrier: count & phase on separate L2 lines/LTS slices ----
        if (tid == 0) {
            unsigned target = (unsigned)(t + 1);
            unsigned old;
            asm volatile("atom.add.release.gpu.global.u32 %0, [%1], 1;"
                         : "=r"(old) : "l"(&g_count.v) : "memory");
            if (old == NBLK - 1) {
                g_count.v = 0;
                asm volatile("st.release.gpu.global.u32 [%0], %1;"
                             :: "l"(&g_phase.v), "r"(target) : "memory");
            } else {
                unsigned ph;
                do {
                    asm volatile("ld.acquire.gpu.global.u32 %0, [%1];"
                                 : "=r"(ph) : "l"(&g_phase.v) : "memory");
                    if (ph < target) __nanosleep(64);
                } while (ph < target);
            }
        }
        __syncthreads();
    }
}

// ---------------- #5: objf = sum_b [ log(A_T . F) + sum_t log s_t ] ---------
__global__ void k_final(const float* __restrict__ final_logp, float* __restrict__ out) {
    __shared__ float red[256];
    const __half* At = g_A[TT & 1];
    int b = threadIdx.x & 63;
    int c = threadIdx.x >> 6;
    float acc = 0.0f;
    for (int s = c; s < SS; s += 4)
        acc += __half2float(At[s * BB + b]) * expf(final_logp[s]);
    red[threadIdx.x] = acc;
    __syncthreads();
    if (c == 0) {
        float dot = red[b] + red[64 + b] + red[128 + b] + red[192 + b];
        float lg = logf(dot);
        for (int t = 0; t < TT; t++) lg += logf(g_csum[t * BB + b]);
        red[b] = lg;
    }
    __syncthreads();
    if (threadIdx.x == 0) {
        float s = 0.0f;
        for (int bb = 0; bb < BB; bb++) s += red[bb];
        out[0] = s;
    }
}

// ---------------- launch -----------------------------------------------------
extern "C" void kernel_launch(void* const* d_in, const int* in_sizes, int n_in,
                              void* d_out, int out_size) {
    const float* input      = (const float*)d_in[0];
    const float* trans_logw = (const float*)d_in[1];
    const float* init_logp  = (const float*)d_in[2];
    const float* final_logp = (const float*)d_in[3];
    const int*   from_state = (const int*)d_in[4];
    const int*   to_state   = (const int*)d_in[5];
    const int*   pdf_id     = (const int*)d_in[6];
    float* out = (float*)d_out;

    dim3 gT((DD + 31) / 32, BB / 32, TT);
    k_exp_T<<<gT, dim3(32, 32)>>>(input);                       // launch 1
    k_init_hist<<<(SS * BB + 255) / 256, 256>>>(init_logp, to_state);   // launch 2
    k_scan_scatter<<<1, 1024>>>(init_logp, to_state, from_state,
                                pdf_id, trans_logw);            // launch 3
    k_forward<<<NBLK, NTHR>>>();                                // launch 4 (profiled)
    k_final<<<1, 256>>>(final_logp, out);                       // launch 5
}